// round 6
// baseline (speedup 1.0000x reference)
#include <cuda_runtime.h>
#include <cstdint>

// ---------------------------------------------------------------------------
// GAT layer, fp32.  Fixed shapes from the reference:
//   N=50000 nodes, E=800000 edges, IN=256, H=4 heads, F=64, H*F=256
// Pipeline (8 launches, one stream, graph-capturable):
//   1. init        : zero denom, reset global-max
//   2. gemm (x@W)        -> g_proj       [N,256]
//   3. gemm (x@skip_w)   -> d_out        [N,256]   (skip connection base)
//   4. score       : s_src/s_trg = <proj, a_src/a_trg> per (node, head)
//   5. edge_score  : e = leaky(s_src[src]+s_trg[trg]); global max via atomicMax
//   6. exp/denom   : ex = exp(e - max); segment-sum into denom via atomicAdd
//   7. aggregate   : d_out[trg] += proj[src] * ex/(denom[trg]+1e-16)  (red.v4)
//   8. epilogue    : d_out = leaky(d_out + bias)
// ---------------------------------------------------------------------------

#define N_NODES 50000
#define N_EDGES 800000
#define IN_DIM  256
#define H       4
#define F       64
#define HF      256
#define NEG     0.2f

// -------- scratch (static device globals; allocation-free) -----------------
__device__ float    g_proj [N_NODES * HF];   // 51.2 MB (L2-resident during agg)
__device__ float    g_ssrc [N_NODES * H];
__device__ float    g_strg [N_NODES * H];
__device__ float    g_edge [N_EDGES * H];    // e, then overwritten with exp(e-max)
__device__ float    g_denom[N_NODES * H];
__device__ unsigned g_maxu;

// order-preserving float<->uint encoding for atomicMax over signed floats
__device__ __forceinline__ unsigned fenc(float f) {
    unsigned u = __float_as_uint(f);
    return (u & 0x80000000u) ? ~u : (u | 0x80000000u);
}
__device__ __forceinline__ float fdec(unsigned u) {
    return (u & 0x80000000u) ? __uint_as_float(u & 0x7fffffffu)
                             : __uint_as_float(~u);
}

// -------- 1. init -----------------------------------------------------------
__global__ void init_kernel() {
    int i = blockIdx.x * blockDim.x + threadIdx.x;
    if (i < N_NODES * H) g_denom[i] = 0.0f;
    if (i == 0) g_maxu = 0u;   // decodes below any finite float's encoding
}

// -------- 2/3. tiled fp32 GEMM: C[M,256] = A[M,256] @ B[256,256] ------------
// 128x128 tile, BK=8, 256 threads, 8x8 micro-tile per thread.
__global__ void __launch_bounds__(256)
gemm_kernel(const float* __restrict__ A, const float* __restrict__ B,
            float* __restrict__ C, int M) {
    __shared__ __align__(16) float As[8][128];
    __shared__ __align__(16) float Bs[8][128];

    const int t  = threadIdx.x;
    const int tx = t & 15;        // 0..15  -> n micro-tile
    const int ty = t >> 4;        // 0..15  -> m micro-tile
    const int m0 = blockIdx.x * 128;
    const int n0 = blockIdx.y * 128;

    float acc[8][8];
#pragma unroll
    for (int i = 0; i < 8; i++)
#pragma unroll
        for (int j = 0; j < 8; j++) acc[i][j] = 0.0f;

    const int a_m  = t >> 1;          // 0..127
    const int a_k4 = (t & 1) * 4;     // 0 or 4
    const int b_k  = t >> 5;          // 0..7
    const int b_n4 = (t & 31) * 4;    // 0..124

    for (int k0 = 0; k0 < IN_DIM; k0 += 8) {
        // load A tile (transposed into smem), guard the M edge
        float4 av = make_float4(0.f, 0.f, 0.f, 0.f);
        int gm = m0 + a_m;
        if (gm < M)
            av = *reinterpret_cast<const float4*>(&A[(size_t)gm * IN_DIM + k0 + a_k4]);
        As[a_k4 + 0][a_m] = av.x;
        As[a_k4 + 1][a_m] = av.y;
        As[a_k4 + 2][a_m] = av.z;
        As[a_k4 + 3][a_m] = av.w;
        // load B tile (row-major, fully coalesced)
        *reinterpret_cast<float4*>(&Bs[b_k][b_n4]) =
            *reinterpret_cast<const float4*>(&B[(size_t)(k0 + b_k) * 256 + n0 + b_n4]);
        __syncthreads();

#pragma unroll
        for (int kk = 0; kk < 8; kk++) {
            float4 a0 = *reinterpret_cast<const float4*>(&As[kk][ty * 8]);
            float4 a1 = *reinterpret_cast<const float4*>(&As[kk][ty * 8 + 4]);
            float4 b0 = *reinterpret_cast<const float4*>(&Bs[kk][tx * 8]);
            float4 b1 = *reinterpret_cast<const float4*>(&Bs[kk][tx * 8 + 4]);
            float ar[8] = {a0.x, a0.y, a0.z, a0.w, a1.x, a1.y, a1.z, a1.w};
            float br[8] = {b0.x, b0.y, b0.z, b0.w, b1.x, b1.y, b1.z, b1.w};
#pragma unroll
            for (int i = 0; i < 8; i++)
#pragma unroll
                for (int j = 0; j < 8; j++)
                    acc[i][j] = fmaf(ar[i], br[j], acc[i][j]);
        }
        __syncthreads();
    }

#pragma unroll
    for (int i = 0; i < 8; i++) {
        int gm = m0 + ty * 8 + i;
        if (gm < M) {
            float* cp = &C[(size_t)gm * 256 + n0 + tx * 8];
            *reinterpret_cast<float4*>(cp) =
                make_float4(acc[i][0], acc[i][1], acc[i][2], acc[i][3]);
            *reinterpret_cast<float4*>(cp + 4) =
                make_float4(acc[i][4], acc[i][5], acc[i][6], acc[i][7]);
        }
    }
}

// -------- 4. per-(node,head) attention dot products -------------------------
// one warp per (n,h): each lane covers 2 of the 64 features
__global__ void __launch_bounds__(256)
score_kernel(const float* __restrict__ a_src, const float* __restrict__ a_trg) {
    int warp = (blockIdx.x * blockDim.x + threadIdx.x) >> 5;
    int lane = threadIdx.x & 31;
    if (warp >= N_NODES * H) return;
    int n = warp >> 2;       // H == 4
    int h = warp & 3;
    const float* p = g_proj + (size_t)n * HF + h * F;
    float v0 = p[lane], v1 = p[lane + 32];
    float as = v0 * a_src[h * F + lane] + v1 * a_src[h * F + lane + 32];
    float at = v0 * a_trg[h * F + lane] + v1 * a_trg[h * F + lane + 32];
#pragma unroll
    for (int o = 16; o; o >>= 1) {
        as += __shfl_down_sync(0xffffffffu, as, o);
        at += __shfl_down_sync(0xffffffffu, at, o);
    }
    if (lane == 0) { g_ssrc[warp] = as; g_strg[warp] = at; }
}

// -------- 5. edge scoring + global max --------------------------------------
// one thread per (edge, head); E*H = 3,200,000 is an exact multiple of 256
__global__ void __launch_bounds__(256)
edge_score_kernel(const int* __restrict__ esrc, const int* __restrict__ etrg) {
    int i    = blockIdx.x * blockDim.x + threadIdx.x;
    int eid  = i >> 2;
    int h    = i & 3;
    int s    = esrc[eid];
    int tg   = etrg[eid];
    float v  = g_ssrc[s * H + h] + g_strg[tg * H + h];
    float e  = (v > 0.0f) ? v : NEG * v;   // leaky relu scoring
    g_edge[i] = e;

    // block max -> one atomicMax per block
    __shared__ float sm[8];
    float m = e;
#pragma unroll
    for (int o = 16; o; o >>= 1) m = fmaxf(m, __shfl_down_sync(0xffffffffu, m, o));
    if ((threadIdx.x & 31) == 0) sm[threadIdx.x >> 5] = m;
    __syncthreads();
    if (threadIdx.x < 8) {
        m = sm[threadIdx.x];
#pragma unroll
        for (int o = 4; o; o >>= 1) m = fmaxf(m, __shfl_down_sync(0x000000ffu, m, o));
        if (threadIdx.x == 0) atomicMax(&g_maxu, fenc(m));
    }
}

// -------- 6. exp + segment-sum denominator ----------------------------------
__global__ void __launch_bounds__(256)
exp_denom_kernel(const int* __restrict__ etrg) {
    int i   = blockIdx.x * blockDim.x + threadIdx.x;
    int eid = i >> 2;
    int h   = i & 3;
    float gm = fdec(g_maxu);
    float ex = expf(g_edge[i] - gm);
    g_edge[i] = ex;
    atomicAdd(&g_denom[etrg[eid] * H + h], ex);
}

// -------- 7. weighted scatter aggregation -----------------------------------
// one warp per edge; each lane handles 8 contiguous features (head = lane>>3);
// scatter via vectorized reductions (red.global.add.v4.f32, sm_90+)
__global__ void __launch_bounds__(256)
agg_kernel(const int* __restrict__ esrc, const int* __restrict__ etrg,
           float* __restrict__ out) {
    int w = (blockIdx.x * blockDim.x + threadIdx.x) >> 5;
    if (w >= N_EDGES) return;
    int lane = threadIdx.x & 31;
    int s  = esrc[w];
    int tg = etrg[w];
    int h  = lane >> 3;   // 64 feats/head, 8 feats/lane
    float attn = g_edge[w * H + h] / (g_denom[tg * H + h] + 1e-16f);

    const float4* p = reinterpret_cast<const float4*>(g_proj + (size_t)s * HF) + lane * 2;
    float4 v0 = p[0];
    float4 v1 = p[1];
    float* o = out + (size_t)tg * HF + lane * 8;
    asm volatile("red.global.add.v4.f32 [%0], {%1,%2,%3,%4};"
                 :: "l"(o),
                    "f"(v0.x * attn), "f"(v0.y * attn),
                    "f"(v0.z * attn), "f"(v0.w * attn) : "memory");
    asm volatile("red.global.add.v4.f32 [%0], {%1,%2,%3,%4};"
                 :: "l"(o + 4),
                    "f"(v1.x * attn), "f"(v1.y * attn),
                    "f"(v1.z * attn), "f"(v1.w * attn) : "memory");
}

// -------- 8. epilogue: bias + output LeakyReLU ------------------------------
__global__ void __launch_bounds__(256)
final_kernel(float* __restrict__ out, const float* __restrict__ bias) {
    int i = blockIdx.x * blockDim.x + threadIdx.x;
    if (i < N_NODES * HF) {
        float v = out[i] + bias[i & (HF - 1)];
        out[i] = (v > 0.0f) ? v : NEG * v;
    }
}

// ---------------------------------------------------------------------------
extern "C" void kernel_launch(void* const* d_in, const int* in_sizes, int n_in,
                              void* d_out, int out_size) {
    const float* x      = (const float*)d_in[0];
    const float* W      = (const float*)d_in[1];
    const float* a_src  = (const float*)d_in[2];
    const float* a_trg  = (const float*)d_in[3];
    const float* skip_w = (const float*)d_in[4];
    const float* bias   = (const float*)d_in[5];
    const int*   esrc   = (const int*)d_in[6];
    const int*   etrg   = (const int*)d_in[7];
    float*       out    = (float*)d_out;

    void* proj_ptr = nullptr;
    cudaGetSymbolAddress(&proj_ptr, g_proj);   // host-side lookup, no allocation

    // 1. init
    init_kernel<<<(N_NODES * H + 255) / 256, 256>>>();

    // 2/3. projections (feature GEMM into scratch, skip GEMM straight into out)
    dim3 ggrid((N_NODES + 127) / 128, 2);
    gemm_kernel<<<ggrid, 256>>>(x, W,      (float*)proj_ptr, N_NODES);
    gemm_kernel<<<ggrid, 256>>>(x, skip_w, out,              N_NODES);

    // 4. per-(node,head) scores: one warp each
    score_kernel<<<(N_NODES * H * 32 + 255) / 256, 256>>>(a_src, a_trg);

    // 5. edge scoring + global max   (E*H/256 = 12500 exactly)
    edge_score_kernel<<<(N_EDGES * H) / 256, 256>>>(esrc, etrg);

    // 6. exp + denominator segment-sum
    exp_denom_kernel<<<(N_EDGES * H) / 256, 256>>>(etrg);

    // 7. scatter aggregation: one warp per edge
    agg_kernel<<<(N_EDGES * 32 + 255) / 256, 256>>>(esrc, etrg, out);

    // 8. bias + leaky relu epilogue
    final_kernel<<<(N_NODES * HF + 255) / 256, 256>>>(out, bias);
}

// round 8
// speedup vs baseline: 1.5038x; 1.5038x over previous
#include <cuda_runtime.h>
#include <cstdint>

// ---------------------------------------------------------------------------
// GAT layer. Fixed shapes: N=50000, E=800000, IN=256, H=4, F=64, HF=256
// Pipeline (7 launches):
//   1. init                  : zero denom, reset global max
//   2. gemm_tf32 (grid.y=4)  : x@W -> g_proj  AND  x@skip_w -> d_out
//   3. score                 : s_src/s_trg per (node, head)
//   4. edge_score            : e = leaky(s_src[src]+s_trg[trg]); global max
//   5. exp/denom             : ex = exp(e-max); segment-sum denom
//   6. aggregate             : d_out[trg] += proj[src]*attn  (red.global.v4)
//   7. epilogue              : d_out = leaky(d_out + bias)
// ---------------------------------------------------------------------------

#define N_NODES 50000
#define N_EDGES 800000
#define IN_DIM  256
#define H       4
#define F       64
#define HF      256
#define NEG     0.2f

// -------- scratch (static device globals; allocation-free) -----------------
__device__ float    g_proj [N_NODES * HF];   // 51.2 MB
__device__ float    g_ssrc [N_NODES * H];
__device__ float    g_strg [N_NODES * H];
__device__ float    g_edge [N_EDGES * H];
__device__ float    g_denom[N_NODES * H];
__device__ unsigned g_maxu;

__device__ __forceinline__ unsigned fenc(float f) {
    unsigned u = __float_as_uint(f);
    return (u & 0x80000000u) ? ~u : (u | 0x80000000u);
}
__device__ __forceinline__ float fdec(unsigned u) {
    return (u & 0x80000000u) ? __uint_as_float(u & 0x7fffffffu)
                             : __uint_as_float(~u);
}

__device__ __forceinline__ unsigned f2tf32(float x) {
    unsigned r;
    asm("cvt.rna.tf32.f32 %0, %1;" : "=r"(r) : "f"(x));
    return r;
}

__device__ __forceinline__ void mma_tf32(float* c,
                                         unsigned a0, unsigned a1,
                                         unsigned a2, unsigned a3,
                                         unsigned b0, unsigned b1) {
    asm volatile(
        "mma.sync.aligned.m16n8k8.row.col.f32.tf32.tf32.f32 "
        "{%0,%1,%2,%3}, {%4,%5,%6,%7}, {%8,%9}, {%0,%1,%2,%3};"
        : "+f"(c[0]), "+f"(c[1]), "+f"(c[2]), "+f"(c[3])
        : "r"(a0), "r"(a1), "r"(a2), "r"(a3), "r"(b0), "r"(b1));
}

// -------- 1. init -----------------------------------------------------------
__global__ void init_kernel() {
    int i = blockIdx.x * blockDim.x + threadIdx.x;
    if (i < N_NODES * H) g_denom[i] = 0.0f;
    if (i == 0) g_maxu = 0u;
}

// -------- 2. fused TF32 MMA GEMM -------------------------------------------
// C[M,256] = A[M,256] @ B[256,256] for two (B,C) pairs selected by blockIdx.y.
// Block tile 128x128, BK=32, 8 warps (4 along M x 2 along N), warp tile 32x64.
// Smem padded: As stride 36 (banks 4m+k distinct), Bs stride 136 (8k+n distinct).
__global__ void __launch_bounds__(256)
gemm_tf32_kernel(const float* __restrict__ A,
                 const float* __restrict__ B0, const float* __restrict__ B1,
                 float* __restrict__ C0, float* __restrict__ C1, int M) {
    __shared__ __align__(16) float As[128][36];   // [m][k]
    __shared__ __align__(16) float Bs[32][136];   // [k][n]

    const float* B = (blockIdx.y < 2) ? B0 : B1;
    float*       C = (blockIdx.y < 2) ? C0 : C1;
    const int n0 = (blockIdx.y & 1) * 128;
    const int m0 = blockIdx.x * 128;

    const int t    = threadIdx.x;
    const int lane = t & 31;
    const int w    = t >> 5;
    const int wm   = (w & 3) * 32;   // warp m offset in block
    const int wn   = (w >> 2) * 64;  // warp n offset in block
    const int lr   = lane >> 2;      // 0..7
    const int lc   = lane & 3;       // 0..3

    float acc[2][8][4];
#pragma unroll
    for (int mt = 0; mt < 2; mt++)
#pragma unroll
        for (int nt = 0; nt < 8; nt++)
#pragma unroll
            for (int i = 0; i < 4; i++) acc[mt][nt][i] = 0.0f;

    // staging coords
    const int ar = t >> 1;           // 0..127 (A row within tile)
    const int ac = (t & 1) * 16;     // A k-offset (covers 16 floats)
    const int br = t >> 3;           // 0..31  (B k row)
    const int bc0 = (t & 7) * 4;     // B n-offset, +32 strides

    for (int k0 = 0; k0 < IN_DIM; k0 += 32) {
        // ---- stage A tile (convert to tf32 bits) ----
        int gm = m0 + ar;
#pragma unroll
        for (int j = 0; j < 4; j++) {
            float4 v = make_float4(0.f, 0.f, 0.f, 0.f);
            if (gm < M)
                v = *reinterpret_cast<const float4*>(
                        &A[(size_t)gm * IN_DIM + k0 + ac + j * 4]);
            int kk = ac + j * 4;
            As[ar][kk + 0] = __uint_as_float(f2tf32(v.x));
            As[ar][kk + 1] = __uint_as_float(f2tf32(v.y));
            As[ar][kk + 2] = __uint_as_float(f2tf32(v.z));
            As[ar][kk + 3] = __uint_as_float(f2tf32(v.w));
        }
        // ---- stage B tile ----
#pragma unroll
        for (int j = 0; j < 4; j++) {
            int nc = bc0 + j * 32;
            float4 v = *reinterpret_cast<const float4*>(
                           &B[(size_t)(k0 + br) * 256 + n0 + nc]);
            Bs[br][nc + 0] = __uint_as_float(f2tf32(v.x));
            Bs[br][nc + 1] = __uint_as_float(f2tf32(v.y));
            Bs[br][nc + 2] = __uint_as_float(f2tf32(v.z));
            Bs[br][nc + 3] = __uint_as_float(f2tf32(v.w));
        }
        __syncthreads();

#pragma unroll
        for (int kk = 0; kk < 32; kk += 8) {
            unsigned af[2][4], bf[8][2];
#pragma unroll
            for (int mt = 0; mt < 2; mt++) {
                int mb = wm + mt * 16;
                af[mt][0] = __float_as_uint(As[mb + lr    ][kk + lc    ]);
                af[mt][1] = __float_as_uint(As[mb + lr + 8][kk + lc    ]);
                af[mt][2] = __float_as_uint(As[mb + lr    ][kk + lc + 4]);
                af[mt][3] = __float_as_uint(As[mb + lr + 8][kk + lc + 4]);
            }
#pragma unroll
            for (int nt = 0; nt < 8; nt++) {
                int nb = wn + nt * 8 + lr;
                bf[nt][0] = __float_as_uint(Bs[kk + lc    ][nb]);
                bf[nt][1] = __float_as_uint(Bs[kk + lc + 4][nb]);
            }
#pragma unroll
            for (int mt = 0; mt < 2; mt++)
#pragma unroll
                for (int nt = 0; nt < 8; nt++)
                    mma_tf32(acc[mt][nt],
                             af[mt][0], af[mt][1], af[mt][2], af[mt][3],
                             bf[nt][0], bf[nt][1]);
        }
        __syncthreads();
    }

    // ---- epilogue ----
#pragma unroll
    for (int mt = 0; mt < 2; mt++) {
#pragma unroll
        for (int nt = 0; nt < 8; nt++) {
            int col  = n0 + wn + nt * 8 + lc * 2;
            int row0 = m0 + wm + mt * 16 + lr;
            int row1 = row0 + 8;
            if (row0 < M)
                *reinterpret_cast<float2*>(&C[(size_t)row0 * 256 + col]) =
                    make_float2(acc[mt][nt][0], acc[mt][nt][1]);
            if (row1 < M)
                *reinterpret_cast<float2*>(&C[(size_t)row1 * 256 + col]) =
                    make_float2(acc[mt][nt][2], acc[mt][nt][3]);
        }
    }
}

// -------- 3. per-(node,head) attention dot products -------------------------
__global__ void __launch_bounds__(256)
score_kernel(const float* __restrict__ a_src, const float* __restrict__ a_trg) {
    int warp = (blockIdx.x * blockDim.x + threadIdx.x) >> 5;
    int lane = threadIdx.x & 31;
    if (warp >= N_NODES * H) return;
    int n = warp >> 2;
    int h = warp & 3;
    const float* p = g_proj + (size_t)n * HF + h * F;
    float v0 = p[lane], v1 = p[lane + 32];
    float as = v0 * a_src[h * F + lane] + v1 * a_src[h * F + lane + 32];
    float at = v0 * a_trg[h * F + lane] + v1 * a_trg[h * F + lane + 32];
#pragma unroll
    for (int o = 16; o; o >>= 1) {
        as += __shfl_down_sync(0xffffffffu, as, o);
        at += __shfl_down_sync(0xffffffffu, at, o);
    }
    if (lane == 0) { g_ssrc[warp] = as; g_strg[warp] = at; }
}

// -------- 4. edge scoring + global max --------------------------------------
__global__ void __launch_bounds__(256)
edge_score_kernel(const int* __restrict__ esrc, const int* __restrict__ etrg) {
    int i   = blockIdx.x * blockDim.x + threadIdx.x;
    int eid = i >> 2;
    int h   = i & 3;
    int s   = esrc[eid];
    int tg  = etrg[eid];
    float v = g_ssrc[s * H + h] + g_strg[tg * H + h];
    float e = (v > 0.0f) ? v : NEG * v;
    g_edge[i] = e;

    __shared__ float sm[8];
    float m = e;
#pragma unroll
    for (int o = 16; o; o >>= 1) m = fmaxf(m, __shfl_down_sync(0xffffffffu, m, o));
    if ((threadIdx.x & 31) == 0) sm[threadIdx.x >> 5] = m;
    __syncthreads();
    if (threadIdx.x < 8) {
        m = sm[threadIdx.x];
#pragma unroll
        for (int o = 4; o; o >>= 1) m = fmaxf(m, __shfl_down_sync(0x000000ffu, m, o));
        if (threadIdx.x == 0) atomicMax(&g_maxu, fenc(m));
    }
}

// -------- 5. exp + segment-sum denominator ----------------------------------
__global__ void __launch_bounds__(256)
exp_denom_kernel(const int* __restrict__ etrg) {
    int i   = blockIdx.x * blockDim.x + threadIdx.x;
    int eid = i >> 2;
    int h   = i & 3;
    float gm = fdec(g_maxu);
    float ex = expf(g_edge[i] - gm);
    g_edge[i] = ex;
    atomicAdd(&g_denom[etrg[eid] * H + h], ex);
}

// -------- 6. weighted scatter aggregation -----------------------------------
__global__ void __launch_bounds__(256)
agg_kernel(const int* __restrict__ esrc, const int* __restrict__ etrg,
           float* __restrict__ out) {
    int w = (blockIdx.x * blockDim.x + threadIdx.x) >> 5;
    if (w >= N_EDGES) return;
    int lane = threadIdx.x & 31;
    int s  = esrc[w];
    int tg = etrg[w];
    int h  = lane >> 3;
    float attn = g_edge[w * H + h] / (g_denom[tg * H + h] + 1e-16f);

    const float4* p = reinterpret_cast<const float4*>(g_proj + (size_t)s * HF) + lane * 2;
    float4 v0 = p[0];
    float4 v1 = p[1];
    float* o = out + (size_t)tg * HF + lane * 8;
    asm volatile("red.global.add.v4.f32 [%0], {%1,%2,%3,%4};"
                 :: "l"(o),
                    "f"(v0.x * attn), "f"(v0.y * attn),
                    "f"(v0.z * attn), "f"(v0.w * attn) : "memory");
    asm volatile("red.global.add.v4.f32 [%0], {%1,%2,%3,%4};"
                 :: "l"(o + 4),
                    "f"(v1.x * attn), "f"(v1.y * attn),
                    "f"(v1.z * attn), "f"(v1.w * attn) : "memory");
}

// -------- 7. epilogue: bias + output LeakyReLU ------------------------------
__global__ void __launch_bounds__(256)
final_kernel(float* __restrict__ out, const float* __restrict__ bias) {
    int i = blockIdx.x * blockDim.x + threadIdx.x;
    if (i < N_NODES * HF) {
        float v = out[i] + bias[i & (HF - 1)];
        out[i] = (v > 0.0f) ? v : NEG * v;
    }
}

// ---------------------------------------------------------------------------
extern "C" void kernel_launch(void* const* d_in, const int* in_sizes, int n_in,
                              void* d_out, int out_size) {
    const float* x      = (const float*)d_in[0];
    const float* W      = (const float*)d_in[1];
    const float* a_src  = (const float*)d_in[2];
    const float* a_trg  = (const float*)d_in[3];
    const float* skip_w = (const float*)d_in[4];
    const float* bias   = (const float*)d_in[5];
    const int*   esrc   = (const int*)d_in[6];
    const int*   etrg   = (const int*)d_in[7];
    float*       out    = (float*)d_out;

    void* proj_ptr = nullptr;
    cudaGetSymbolAddress(&proj_ptr, g_proj);

    // 1. init
    init_kernel<<<(N_NODES * H + 255) / 256, 256>>>();

    // 2. fused TF32 tensor-core GEMMs: x@W -> proj, x@skip_w -> out
    dim3 ggrid((N_NODES + 127) / 128, 4);
    gemm_tf32_kernel<<<ggrid, 256>>>(x, W, skip_w, (float*)proj_ptr, out, N_NODES);

    // 3. per-(node,head) scores
    score_kernel<<<(N_NODES * H * 32 + 255) / 256, 256>>>(a_src, a_trg);

    // 4. edge scoring + global max
    edge_score_kernel<<<(N_EDGES * H) / 256, 256>>>(esrc, etrg);

    // 5. exp + denominator
    exp_denom_kernel<<<(N_EDGES * H) / 256, 256>>>(etrg);

    // 6. scatter aggregation
    agg_kernel<<<(N_EDGES * 32 + 255) / 256, 256>>>(esrc, etrg, out);

    // 7. bias + leaky relu
    final_kernel<<<(N_NODES * HF + 255) / 256, 256>>>(out, bias);
}

// round 13
// speedup vs baseline: 2.1773x; 1.4479x over previous
#include <cuda_runtime.h>
#include <cstdint>

// ---------------------------------------------------------------------------
// GAT layer. Fixed shapes: N=50000, E=800000, IN=256, H=4, F=64, HF=256
// Pipeline:
//   0. memset      : deg = cur = 0
//   1. count       : deg[trg]++
//   2. scan        : exclusive prefix -> off[N+1]   (single block)
//   3. scatter     : CSR of incoming edges (csr_src, csr_eid)
//   4. gemm_tf32   : x@W -> g_proj (+ fused s_src/s_trg scores), x@skip_w -> out
//   5. edge_ex     : ex = exp(leaky(s_src[src]+s_trg[trg]))     (no global max:
//                    mathematically equivalent, see analysis)
//   6. agg         : warp per node: out = Σ proj[src]*ex / Σ ex + skip + bias,
//                    leaky  (register accumulation, plain stores, no atomics)
// ---------------------------------------------------------------------------

#define N_NODES 50000
#define N_EDGES 800000
#define IN_DIM  256
#define H       4
#define F       64
#define HF      256
#define NEG     0.2f

// -------- scratch (static device globals; allocation-free) -----------------
__device__ float g_proj   [N_NODES * HF];    // 51.2 MB
__device__ float g_ssrc   [N_NODES * H];
__device__ float g_strg   [N_NODES * H];
__device__ float g_edge   [N_EDGES * H];     // exp(e) per (edge, head)
__device__ int   g_deg    [N_NODES];
__device__ int   g_cur    [N_NODES];
__device__ int   g_off    [N_NODES + 1];
__device__ int   g_csr_src[N_EDGES];
__device__ int   g_csr_eid[N_EDGES];

__device__ __forceinline__ unsigned f2tf32(float x) {
    unsigned r;
    asm("cvt.rna.tf32.f32 %0, %1;" : "=r"(r) : "f"(x));
    return r;
}

__device__ __forceinline__ void mma_tf32(float* c,
                                         unsigned a0, unsigned a1,
                                         unsigned a2, unsigned a3,
                                         unsigned b0, unsigned b1) {
    asm volatile(
        "mma.sync.aligned.m16n8k8.row.col.f32.tf32.tf32.f32 "
        "{%0,%1,%2,%3}, {%4,%5,%6,%7}, {%8,%9}, {%0,%1,%2,%3};"
        : "+f"(c[0]), "+f"(c[1]), "+f"(c[2]), "+f"(c[3])
        : "r"(a0), "r"(a1), "r"(a2), "r"(a3), "r"(b0), "r"(b1));
}

// -------- 1. degree histogram ----------------------------------------------
__global__ void __launch_bounds__(256)
count_kernel(const int* __restrict__ etrg) {
    int i = blockIdx.x * blockDim.x + threadIdx.x;
    if (i < N_EDGES) atomicAdd(&g_deg[etrg[i]], 1);
}

// -------- 2. exclusive prefix sum over degrees (one block) ------------------
#define SCAN_T 1024
#define CHUNK  49           // ceil(50000/1024)
__global__ void __launch_bounds__(SCAN_T)
scan_kernel() {
    __shared__ int sm[SCAN_T];
    int t   = threadIdx.x;
    int beg = t * CHUNK;
    int end = min(beg + CHUNK, N_NODES);
    int s = 0;
    for (int i = beg; i < end; i++) s += g_deg[i];
    sm[t] = s;
    __syncthreads();
    // inclusive Hillis-Steele scan
    for (int o = 1; o < SCAN_T; o <<= 1) {
        int v = (t >= o) ? sm[t - o] : 0;
        __syncthreads();
        if (t >= o) sm[t] += v;
        __syncthreads();
    }
    int base = (t > 0) ? sm[t - 1] : 0;
    for (int i = beg; i < end; i++) { g_off[i] = base; base += g_deg[i]; }
    if (t == 0) g_off[N_NODES] = sm[SCAN_T - 1];
}

// -------- 3. CSR scatter ----------------------------------------------------
__global__ void __launch_bounds__(256)
scatter_kernel(const int* __restrict__ esrc, const int* __restrict__ etrg) {
    int i = blockIdx.x * blockDim.x + threadIdx.x;
    if (i >= N_EDGES) return;
    int tg  = etrg[i];
    int pos = g_off[tg] + atomicAdd(&g_cur[tg], 1);
    g_csr_src[pos] = esrc[i];
    g_csr_eid[pos] = i;
}

// -------- 4. fused TF32 MMA GEMM (+ score epilogue on the proj path) --------
// C[M,256] = A[M,256] @ B[256,256]; blockIdx.y selects (B,C) pair and n-half.
// Block tile 128x128, BK=32, 8 warps (4 M x 2 N), warp tile 32x64.
// For y<2 (proj), each warp tile spans exactly one head's 64 features, so
// s_src/s_trg reduce straight from the accumulator fragments.
__global__ void __launch_bounds__(256)
gemm_tf32_kernel(const float* __restrict__ A,
                 const float* __restrict__ B0, const float* __restrict__ B1,
                 float* __restrict__ C0, float* __restrict__ C1,
                 const float* __restrict__ a_src, const float* __restrict__ a_trg,
                 int M) {
    __shared__ __align__(16) float As[128][36];   // [m][k]
    __shared__ __align__(16) float Bs[32][136];   // [k][n]

    const bool  is_proj = (blockIdx.y < 2);
    const float* B = is_proj ? B0 : B1;
    float*       C = is_proj ? C0 : C1;
    const int n0 = (blockIdx.y & 1) * 128;
    const int m0 = blockIdx.x * 128;

    const int t    = threadIdx.x;
    const int lane = t & 31;
    const int w    = t >> 5;
    const int wm   = (w & 3) * 32;
    const int wn   = (w >> 2) * 64;
    const int lr   = lane >> 2;
    const int lc   = lane & 3;

    float acc[2][8][4];
#pragma unroll
    for (int mt = 0; mt < 2; mt++)
#pragma unroll
        for (int nt = 0; nt < 8; nt++)
#pragma unroll
            for (int i = 0; i < 4; i++) acc[mt][nt][i] = 0.0f;

    const int ar  = t >> 1;
    const int ac  = (t & 1) * 16;
    const int br  = t >> 3;
    const int bc0 = (t & 7) * 4;

    for (int k0 = 0; k0 < IN_DIM; k0 += 32) {
        int gm = m0 + ar;
#pragma unroll
        for (int j = 0; j < 4; j++) {
            float4 v = make_float4(0.f, 0.f, 0.f, 0.f);
            if (gm < M)
                v = *reinterpret_cast<const float4*>(
                        &A[(size_t)gm * IN_DIM + k0 + ac + j * 4]);
            int kk = ac + j * 4;
            As[ar][kk + 0] = __uint_as_float(f2tf32(v.x));
            As[ar][kk + 1] = __uint_as_float(f2tf32(v.y));
            As[ar][kk + 2] = __uint_as_float(f2tf32(v.z));
            As[ar][kk + 3] = __uint_as_float(f2tf32(v.w));
        }
#pragma unroll
        for (int j = 0; j < 4; j++) {
            int nc = bc0 + j * 32;
            float4 v = *reinterpret_cast<const float4*>(
                           &B[(size_t)(k0 + br) * 256 + n0 + nc]);
            Bs[br][nc + 0] = __uint_as_float(f2tf32(v.x));
            Bs[br][nc + 1] = __uint_as_float(f2tf32(v.y));
            Bs[br][nc + 2] = __uint_as_float(f2tf32(v.z));
            Bs[br][nc + 3] = __uint_as_float(f2tf32(v.w));
        }
        __syncthreads();

#pragma unroll
        for (int kk = 0; kk < 32; kk += 8) {
            unsigned af[2][4], bf[8][2];
#pragma unroll
            for (int mt = 0; mt < 2; mt++) {
                int mb = wm + mt * 16;
                af[mt][0] = __float_as_uint(As[mb + lr    ][kk + lc    ]);
                af[mt][1] = __float_as_uint(As[mb + lr + 8][kk + lc    ]);
                af[mt][2] = __float_as_uint(As[mb + lr    ][kk + lc + 4]);
                af[mt][3] = __float_as_uint(As[mb + lr + 8][kk + lc + 4]);
            }
#pragma unroll
            for (int nt = 0; nt < 8; nt++) {
                int nb = wn + nt * 8 + lr;
                bf[nt][0] = __float_as_uint(Bs[kk + lc    ][nb]);
                bf[nt][1] = __float_as_uint(Bs[kk + lc + 4][nb]);
            }
#pragma unroll
            for (int mt = 0; mt < 2; mt++)
#pragma unroll
                for (int nt = 0; nt < 8; nt++)
                    mma_tf32(acc[mt][nt],
                             af[mt][0], af[mt][1], af[mt][2], af[mt][3],
                             bf[nt][0], bf[nt][1]);
        }
        __syncthreads();
    }

    // ---- store C ----
#pragma unroll
    for (int mt = 0; mt < 2; mt++) {
#pragma unroll
        for (int nt = 0; nt < 8; nt++) {
            int col  = n0 + wn + nt * 8 + lc * 2;
            int row0 = m0 + wm + mt * 16 + lr;
            int row1 = row0 + 8;
            if (row0 < M)
                *reinterpret_cast<float2*>(&C[(size_t)row0 * 256 + col]) =
                    make_float2(acc[mt][nt][0], acc[mt][nt][1]);
            if (row1 < M)
                *reinterpret_cast<float2*>(&C[(size_t)row1 * 256 + col]) =
                    make_float2(acc[mt][nt][2], acc[mt][nt][3]);
        }
    }

    // ---- fused attention-score epilogue (proj path only) ----
    if (is_proj) {
        const int head = (n0 + wn) >> 6;       // this warp covers one full head
        float asv[16], atv[16];
#pragma unroll
        for (int nt = 0; nt < 8; nt++)
#pragma unroll
            for (int i = 0; i < 2; i++) {
                int colh = nt * 8 + lc * 2 + i; // feature index within head
                asv[nt * 2 + i] = a_src[head * F + colh];
                atv[nt * 2 + i] = a_trg[head * F + colh];
            }
#pragma unroll
        for (int mt = 0; mt < 2; mt++)
#pragma unroll
            for (int rh = 0; rh < 2; rh++) {
                float ps = 0.f, pt = 0.f;
#pragma unroll
                for (int nt = 0; nt < 8; nt++)
#pragma unroll
                    for (int i = 0; i < 2; i++) {
                        float c = acc[mt][nt][rh * 2 + i];
                        ps = fmaf(c, asv[nt * 2 + i], ps);
                        pt = fmaf(c, atv[nt * 2 + i], pt);
                    }
                // reduce over the 4 lanes (lc) sharing this row
                ps += __shfl_xor_sync(0xffffffffu, ps, 1);
                ps += __shfl_xor_sync(0xffffffffu, ps, 2);
                pt += __shfl_xor_sync(0xffffffffu, pt, 1);
                pt += __shfl_xor_sync(0xffffffffu, pt, 2);
                if (lc == 0) {
                    int row = m0 + wm + mt * 16 + lr + rh * 8;
                    if (row < M) {
                        g_ssrc[row * H + head] = ps;
                        g_strg[row * H + head] = pt;
                    }
                }
            }
    }
}

// -------- 5. edge scoring -> exp (no global max; no atomics) ----------------
__global__ void __launch_bounds__(256)
edge_ex_kernel(const int* __restrict__ esrc, const int* __restrict__ etrg) {
    int i   = blockIdx.x * blockDim.x + threadIdx.x;
    int eid = i >> 2;
    int h   = i & 3;
    float v = g_ssrc[esrc[eid] * H + h] + g_strg[etrg[eid] * H + h];
    float e = (v > 0.0f) ? v : NEG * v;
    g_edge[i] = expf(e);
}

// -------- 6. gather aggregation + full epilogue -----------------------------
// one warp per target node; per-lane 8 features (head = lane>>3);
// in-register softmax-normalized sum, then skip + bias + leaky, plain store.
__global__ void __launch_bounds__(256)
agg_kernel(float* __restrict__ out, const float* __restrict__ bias) {
    int n = (blockIdx.x * blockDim.x + threadIdx.x) >> 5;
    if (n >= N_NODES) return;
    int lane = threadIdx.x & 31;
    int h    = lane >> 3;

    int beg = g_off[n];
    int end = g_off[n + 1];

    float acc[8];
#pragma unroll
    for (int i = 0; i < 8; i++) acc[i] = 0.0f;
    float den = 0.0f;

    for (int j = beg; j < end; j++) {
        int   s  = g_csr_src[j];                 // broadcast across warp
        int   e  = g_csr_eid[j];
        float ex = g_edge[e * H + h];
        den += ex;
        const float4* p =
            reinterpret_cast<const float4*>(g_proj + (size_t)s * HF) + lane * 2;
        float4 v0 = p[0];
        float4 v1 = p[1];
        acc[0] = fmaf(v0.x, ex, acc[0]);
        acc[1] = fmaf(v0.y, ex, acc[1]);
        acc[2] = fmaf(v0.z, ex, acc[2]);
        acc[3] = fmaf(v0.w, ex, acc[3]);
        acc[4] = fmaf(v1.x, ex, acc[4]);
        acc[5] = fmaf(v1.y, ex, acc[5]);
        acc[6] = fmaf(v1.z, ex, acc[6]);
        acc[7] = fmaf(v1.w, ex, acc[7]);
    }

    float inv = 1.0f / (den + 1e-16f);
    float* o  = out + (size_t)n * HF + lane * 8;
    float4 s0 = *reinterpret_cast<const float4*>(o);
    float4 s1 = *reinterpret_cast<const float4*>(o + 4);
    const float4* bb = reinterpret_cast<const float4*>(bias) + lane * 2;
    float4 b0 = bb[0];
    float4 b1 = bb[1];

    float r[8];
    r[0] = acc[0] * inv + s0.x + b0.x;
    r[1] = acc[1] * inv + s0.y + b0.y;
    r[2] = acc[2] * inv + s0.z + b0.z;
    r[3] = acc[3] * inv + s0.w + b0.w;
    r[4] = acc[4] * inv + s1.x + b1.x;
    r[5] = acc[5] * inv + s1.y + b1.y;
    r[6] = acc[6] * inv + s1.z + b1.z;
    r[7] = acc[7] * inv + s1.w + b1.w;
#pragma unroll
    for (int i = 0; i < 8; i++) r[i] = (r[i] > 0.0f) ? r[i] : NEG * r[i];

    *reinterpret_cast<float4*>(o)     = make_float4(r[0], r[1], r[2], r[3]);
    *reinterpret_cast<float4*>(o + 4) = make_float4(r[4], r[5], r[6], r[7]);
}

// ---------------------------------------------------------------------------
extern "C" void kernel_launch(void* const* d_in, const int* in_sizes, int n_in,
                              void* d_out, int out_size) {
    const float* x      = (const float*)d_in[0];
    const float* W      = (const float*)d_in[1];
    const float* a_src  = (const float*)d_in[2];
    const float* a_trg  = (const float*)d_in[3];
    const float* skip_w = (const float*)d_in[4];
    const float* bias   = (const float*)d_in[5];
    const int*   esrc   = (const int*)d_in[6];
    const int*   etrg   = (const int*)d_in[7];
    float*       out    = (float*)d_out;

    void *proj_ptr = nullptr, *deg_ptr = nullptr, *cur_ptr = nullptr;
    cudaGetSymbolAddress(&proj_ptr, g_proj);
    cudaGetSymbolAddress(&deg_ptr,  g_deg);
    cudaGetSymbolAddress(&cur_ptr,  g_cur);

    // 0. zero histogram + cursors
    cudaMemsetAsync(deg_ptr, 0, N_NODES * sizeof(int));
    cudaMemsetAsync(cur_ptr, 0, N_NODES * sizeof(int));

    // 1-3. CSR build
    count_kernel  <<<(N_EDGES + 255) / 256, 256>>>(etrg);
    scan_kernel   <<<1, SCAN_T>>>();
    scatter_kernel<<<(N_EDGES + 255) / 256, 256>>>(esrc, etrg);

    // 4. fused TF32 GEMMs (+ scores): x@W -> proj, x@skip_w -> out
    dim3 ggrid((N_NODES + 127) / 128, 4);
    gemm_tf32_kernel<<<ggrid, 256>>>(x, W, skip_w, (float*)proj_ptr, out,
                                     a_src, a_trg, N_NODES);

    // 5. per-(edge,head) exp scores
    edge_ex_kernel<<<(N_EDGES * H) / 256, 256>>>(esrc, etrg);

    // 6. gather aggregation + skip + bias + leaky
    agg_kernel<<<(N_NODES * 32 + 255) / 256, 256>>>(out, bias);
}

// round 14
// speedup vs baseline: 3.2272x; 1.4822x over previous
#include <cuda_runtime.h>
#include <cstdint>

// ---------------------------------------------------------------------------
// GAT layer. Fixed shapes: N=50000, E=800000, IN=256, H=4, F=64, HF=256
// Stream 0 : bcvt(B->tf32) -> gemm(cp.async double-buffered, fused scores)
//            -> [wait CSR] -> agg (fused exp + softmax + skip + bias + leaky)
// Stream 2 : memset(deg) -> count -> scan -> scatter      (hidden under GEMM)
// ---------------------------------------------------------------------------

#define N_NODES 50000
#define N_EDGES 800000
#define IN_DIM  256
#define H       4
#define F       64
#define HF      256
#define NEG     0.2f

// -------- scratch (static device globals; allocation-free) -----------------
__device__ float g_proj   [N_NODES * HF];    // 51.2 MB (L2-resident in agg)
__device__ float g_ssrc   [N_NODES * H];
__device__ float g_strg   [N_NODES * H];
__device__ float g_Btf    [2 * 256 * 256];   // W and skip_w as tf32 bits
__device__ int   g_deg    [N_NODES];
__device__ int   g_off    [N_NODES + 1];
__device__ int   g_off2   [N_NODES];         // scatter cursor (starts = g_off)
__device__ int   g_csr_src[N_EDGES];

__device__ __forceinline__ unsigned f2tf32(float x) {
    unsigned r;
    asm("cvt.rna.tf32.f32 %0, %1;" : "=r"(r) : "f"(x));
    return r;
}

__device__ __forceinline__ uint32_t s2u(const void* p) {
    uint32_t a;
    asm("{ .reg .u64 t; cvta.to.shared.u64 t, %1; cvt.u32.u64 %0, t; }"
        : "=r"(a) : "l"(p));
    return a;
}

__device__ __forceinline__ void cp16(uint32_t dst, const void* src, int bytes) {
    asm volatile("cp.async.cg.shared.global [%0], [%1], 16, %2;"
                 :: "r"(dst), "l"(src), "r"(bytes));
}

__device__ __forceinline__ void mma_tf32(float* c,
                                         unsigned a0, unsigned a1,
                                         unsigned a2, unsigned a3,
                                         unsigned b0, unsigned b1) {
    asm volatile(
        "mma.sync.aligned.m16n8k8.row.col.f32.tf32.tf32.f32 "
        "{%0,%1,%2,%3}, {%4,%5,%6,%7}, {%8,%9}, {%0,%1,%2,%3};"
        : "+f"(c[0]), "+f"(c[1]), "+f"(c[2]), "+f"(c[3])
        : "r"(a0), "r"(a1), "r"(a2), "r"(a3), "r"(b0), "r"(b1));
}

// -------- B -> tf32 pre-conversion -----------------------------------------
__global__ void __launch_bounds__(256)
bcvt_kernel(const float* __restrict__ W, const float* __restrict__ SW) {
    int i = blockIdx.x * 256 + threadIdx.x;           // 131072 total
    float v = (i < 65536) ? W[i] : SW[i - 65536];
    g_Btf[i] = __uint_as_float(f2tf32(v));
}

// -------- CSR build ---------------------------------------------------------
__global__ void __launch_bounds__(256)
count_kernel(const int* __restrict__ etrg) {
    int i = blockIdx.x * blockDim.x + threadIdx.x;
    if (i < N_EDGES) atomicAdd(&g_deg[etrg[i]], 1);
}

#define SCAN_T 1024
#define CHUNK  49
__global__ void __launch_bounds__(SCAN_T)
scan_kernel() {
    __shared__ int sm[SCAN_T];
    int t   = threadIdx.x;
    int beg = t * CHUNK;
    int end = min(beg + CHUNK, N_NODES);
    int s = 0;
    for (int i = beg; i < end; i++) s += g_deg[i];
    sm[t] = s;
    __syncthreads();
    for (int o = 1; o < SCAN_T; o <<= 1) {
        int v = (t >= o) ? sm[t - o] : 0;
        __syncthreads();
        if (t >= o) sm[t] += v;
        __syncthreads();
    }
    int base = (t > 0) ? sm[t - 1] : 0;
    for (int i = beg; i < end; i++) {
        g_off[i] = base; g_off2[i] = base; base += g_deg[i];
    }
    if (t == 0) g_off[N_NODES] = sm[SCAN_T - 1];
}

__global__ void __launch_bounds__(256)
scatter_kernel(const int* __restrict__ esrc, const int* __restrict__ etrg) {
    int i = blockIdx.x * blockDim.x + threadIdx.x;
    if (i >= N_EDGES) return;
    int pos = atomicAdd(&g_off2[etrg[i]], 1);
    g_csr_src[pos] = esrc[i];
}

// -------- TF32 MMA GEMM, cp.async double-buffered ---------------------------
// C[M,256] = A[M,256] @ B[256,256]; blockIdx.y in 0..3 selects (B,C,n-half).
// Block tile 128x128, BK=32, 8 warps (4 M x 2 N), warp tile 32x64.
// B comes pre-converted from g_Btf; A converted in-register at fragment load.
#define AS(p,m,k) As[(p)*4608 + (m)*36 + (k)]
#define BS(p,k,n) Bs[(p)*4352 + (k)*136 + (n)]
#define GEMM_SMEM ((2*4608 + 2*4352) * 4)

__global__ void __launch_bounds__(256, 2)
gemm_tf32_kernel(const float* __restrict__ A,
                 float* __restrict__ C0, float* __restrict__ C1,
                 const float* __restrict__ a_src, const float* __restrict__ a_trg,
                 int M) {
    extern __shared__ float smf[];
    float* As = smf;
    float* Bs = smf + 2 * 4608;

    const bool is_proj = (blockIdx.y < 2);
    const float* Bt = g_Btf + (is_proj ? 0 : 65536);
    float*       C  = is_proj ? C0 : C1;
    const int n0 = (blockIdx.y & 1) * 128;
    const int m0 = blockIdx.x * 128;

    const int t    = threadIdx.x;
    const int lane = t & 31;
    const int w    = t >> 5;
    const int wm   = (w & 3) * 32;
    const int wn   = (w >> 2) * 64;
    const int lr   = lane >> 2;
    const int lc   = lane & 3;

    float acc[2][8][4];
#pragma unroll
    for (int mt = 0; mt < 2; mt++)
#pragma unroll
        for (int nt = 0; nt < 8; nt++)
#pragma unroll
            for (int i = 0; i < 4; i++) acc[mt][nt][i] = 0.0f;

    // staging coords
    const int ar  = t >> 1;          // A row 0..127
    const int ac  = (t & 1) * 16;    // A k-offset
    const int br  = t >> 3;          // B k row 0..31
    const int bc0 = (t & 7) * 4;     // B n-offset, +32 strides

    const int      gm    = m0 + ar;
    const int      abyt  = (gm < M) ? 16 : 0;
    const float*   agp   = A + (size_t)gm * IN_DIM + ac;
    const uint32_t asm_b = s2u(&AS(0, ar, ac));
    const float*   bgp   = Bt + (size_t)br * 256 + n0 + bc0;
    const uint32_t bsm_b = s2u(&BS(0, br, bc0));

    // prologue: stage k0=0 into buffer 0
#pragma unroll
    for (int j = 0; j < 4; j++) cp16(asm_b + j * 16, agp + j * 4, abyt);
#pragma unroll
    for (int j = 0; j < 4; j++) cp16(bsm_b + j * 128, bgp + j * 32, 16);
    asm volatile("cp.async.commit_group;");

    int p = 0;
    for (int it = 0; it < 8; it++) {
        if (it < 7) {
            int k0 = (it + 1) * 32;
            uint32_t ad = asm_b + (p ^ 1) * 4608 * 4;
            uint32_t bd = bsm_b + (p ^ 1) * 4352 * 4;
#pragma unroll
            for (int j = 0; j < 4; j++) cp16(ad + j * 16,  agp + k0 + j * 4, abyt);
#pragma unroll
            for (int j = 0; j < 4; j++) cp16(bd + j * 128, bgp + (size_t)k0 * 256 + j * 32, 16);
            asm volatile("cp.async.commit_group;");
            asm volatile("cp.async.wait_group %0;" :: "n"(1));
        } else {
            asm volatile("cp.async.wait_group %0;" :: "n"(0));
        }
        __syncthreads();

#pragma unroll
        for (int kk = 0; kk < 32; kk += 8) {
            unsigned af[2][4], bf[8][2];
#pragma unroll
            for (int mt = 0; mt < 2; mt++) {
                int mb = wm + mt * 16;
                af[mt][0] = f2tf32(AS(p, mb + lr,     kk + lc));
                af[mt][1] = f2tf32(AS(p, mb + lr + 8, kk + lc));
                af[mt][2] = f2tf32(AS(p, mb + lr,     kk + lc + 4));
                af[mt][3] = f2tf32(AS(p, mb + lr + 8, kk + lc + 4));
            }
#pragma unroll
            for (int nt = 0; nt < 8; nt++) {
                int nb = wn + nt * 8 + lr;
                bf[nt][0] = __float_as_uint(BS(p, kk + lc,     nb));
                bf[nt][1] = __float_as_uint(BS(p, kk + lc + 4, nb));
            }
#pragma unroll
            for (int mt = 0; mt < 2; mt++)
#pragma unroll
                for (int nt = 0; nt < 8; nt++)
                    mma_tf32(acc[mt][nt],
                             af[mt][0], af[mt][1], af[mt][2], af[mt][3],
                             bf[nt][0], bf[nt][1]);
        }
        __syncthreads();
        p ^= 1;
    }

    // ---- store C ----
#pragma unroll
    for (int mt = 0; mt < 2; mt++) {
#pragma unroll
        for (int nt = 0; nt < 8; nt++) {
            int col  = n0 + wn + nt * 8 + lc * 2;
            int row0 = m0 + wm + mt * 16 + lr;
            int row1 = row0 + 8;
            if (row0 < M)
                *reinterpret_cast<float2*>(&C[(size_t)row0 * 256 + col]) =
                    make_float2(acc[mt][nt][0], acc[mt][nt][1]);
            if (row1 < M)
                *reinterpret_cast<float2*>(&C[(size_t)row1 * 256 + col]) =
                    make_float2(acc[mt][nt][2], acc[mt][nt][3]);
        }
    }

    // ---- fused attention-score epilogue (proj path only) ----
    if (is_proj) {
        const int head = (n0 + wn) >> 6;
        float asv[16], atv[16];
#pragma unroll
        for (int nt = 0; nt < 8; nt++)
#pragma unroll
            for (int i = 0; i < 2; i++) {
                int colh = nt * 8 + lc * 2 + i;
                asv[nt * 2 + i] = a_src[head * F + colh];
                atv[nt * 2 + i] = a_trg[head * F + colh];
            }
#pragma unroll
        for (int mt = 0; mt < 2; mt++)
#pragma unroll
            for (int rh = 0; rh < 2; rh++) {
                float ps = 0.f, pt = 0.f;
#pragma unroll
                for (int nt = 0; nt < 8; nt++)
#pragma unroll
                    for (int i = 0; i < 2; i++) {
                        float c = acc[mt][nt][rh * 2 + i];
                        ps = fmaf(c, asv[nt * 2 + i], ps);
                        pt = fmaf(c, atv[nt * 2 + i], pt);
                    }
                ps += __shfl_xor_sync(0xffffffffu, ps, 1);
                ps += __shfl_xor_sync(0xffffffffu, ps, 2);
                pt += __shfl_xor_sync(0xffffffffu, pt, 1);
                pt += __shfl_xor_sync(0xffffffffu, pt, 2);
                if (lc == 0) {
                    int row = m0 + wm + mt * 16 + lr + rh * 8;
                    if (row < M) {
                        g_ssrc[row * H + head] = ps;
                        g_strg[row * H + head] = pt;
                    }
                }
            }
    }
}

// -------- aggregation: fused exp + softmax + skip + bias + leaky ------------
// one warp per target node; lane owns 8 features (head = lane>>3);
// 4-edge software pipeline for memory-level parallelism.
__device__ __forceinline__ float edge_ex(float ss, float st) {
    float v = ss + st;
    float e = (v > 0.0f) ? v : NEG * v;
    return expf(e);
}

__global__ void __launch_bounds__(256)
agg_kernel(float* __restrict__ out, const float* __restrict__ bias) {
    int n = (blockIdx.x * blockDim.x + threadIdx.x) >> 5;
    if (n >= N_NODES) return;
    int lane = threadIdx.x & 31;
    int h    = lane >> 3;

    float st  = g_strg[n * H + h];
    int   beg = g_off[n];
    int   end = g_off[n + 1];

    float acc[8];
#pragma unroll
    for (int i = 0; i < 8; i++) acc[i] = 0.0f;
    float den = 0.0f;

    int j = beg;
    for (; j + 4 <= end; j += 4) {
        int s0 = g_csr_src[j],     s1 = g_csr_src[j + 1];
        int s2 = g_csr_src[j + 2], s3 = g_csr_src[j + 3];
        float x0 = g_ssrc[s0 * H + h], x1 = g_ssrc[s1 * H + h];
        float x2 = g_ssrc[s2 * H + h], x3 = g_ssrc[s3 * H + h];
        const float4* p0 = reinterpret_cast<const float4*>(g_proj + (size_t)s0 * HF) + lane * 2;
        const float4* p1 = reinterpret_cast<const float4*>(g_proj + (size_t)s1 * HF) + lane * 2;
        const float4* p2 = reinterpret_cast<const float4*>(g_proj + (size_t)s2 * HF) + lane * 2;
        const float4* p3 = reinterpret_cast<const float4*>(g_proj + (size_t)s3 * HF) + lane * 2;
        float4 a0 = p0[0], b0 = p0[1];
        float4 a1 = p1[0], b1 = p1[1];
        float4 a2 = p2[0], b2 = p2[1];
        float4 a3 = p3[0], b3 = p3[1];
        float e0 = edge_ex(x0, st), e1 = edge_ex(x1, st);
        float e2 = edge_ex(x2, st), e3 = edge_ex(x3, st);
        den += (e0 + e1) + (e2 + e3);
        acc[0] = fmaf(a0.x, e0, fmaf(a1.x, e1, fmaf(a2.x, e2, fmaf(a3.x, e3, acc[0]))));
        acc[1] = fmaf(a0.y, e0, fmaf(a1.y, e1, fmaf(a2.y, e2, fmaf(a3.y, e3, acc[1]))));
        acc[2] = fmaf(a0.z, e0, fmaf(a1.z, e1, fmaf(a2.z, e2, fmaf(a3.z, e3, acc[2]))));
        acc[3] = fmaf(a0.w, e0, fmaf(a1.w, e1, fmaf(a2.w, e2, fmaf(a3.w, e3, acc[3]))));
        acc[4] = fmaf(b0.x, e0, fmaf(b1.x, e1, fmaf(b2.x, e2, fmaf(b3.x, e3, acc[4]))));
        acc[5] = fmaf(b0.y, e0, fmaf(b1.y, e1, fmaf(b2.y, e2, fmaf(b3.y, e3, acc[5]))));
        acc[6] = fmaf(b0.z, e0, fmaf(b1.z, e1, fmaf(b2.z, e2, fmaf(b3.z, e3, acc[6]))));
        acc[7] = fmaf(b0.w, e0, fmaf(b1.w, e1, fmaf(b2.w, e2, fmaf(b3.w, e3, acc[7]))));
    }
    for (; j < end; j++) {
        int   s  = g_csr_src[j];
        float ex = edge_ex(g_ssrc[s * H + h], st);
        den += ex;
        const float4* p = reinterpret_cast<const float4*>(g_proj + (size_t)s * HF) + lane * 2;
        float4 v0 = p[0], v1 = p[1];
        acc[0] = fmaf(v0.x, ex, acc[0]); acc[1] = fmaf(v0.y, ex, acc[1]);
        acc[2] = fmaf(v0.z, ex, acc[2]); acc[3] = fmaf(v0.w, ex, acc[3]);
        acc[4] = fmaf(v1.x, ex, acc[4]); acc[5] = fmaf(v1.y, ex, acc[5]);
        acc[6] = fmaf(v1.z, ex, acc[6]); acc[7] = fmaf(v1.w, ex, acc[7]);
    }

    float inv = 1.0f / (den + 1e-16f);
    float* o  = out + (size_t)n * HF + lane * 8;
    float4 s0 = *reinterpret_cast<const float4*>(o);
    float4 s1 = *reinterpret_cast<const float4*>(o + 4);
    const float4* bb = reinterpret_cast<const float4*>(bias) + lane * 2;
    float4 b0 = bb[0];
    float4 b1 = bb[1];

    float r[8];
    r[0] = acc[0] * inv + s0.x + b0.x;
    r[1] = acc[1] * inv + s0.y + b0.y;
    r[2] = acc[2] * inv + s0.z + b0.z;
    r[3] = acc[3] * inv + s0.w + b0.w;
    r[4] = acc[4] * inv + s1.x + b1.x;
    r[5] = acc[5] * inv + s1.y + b1.y;
    r[6] = acc[6] * inv + s1.z + b1.z;
    r[7] = acc[7] * inv + s1.w + b1.w;
#pragma unroll
    for (int i = 0; i < 8; i++) r[i] = (r[i] > 0.0f) ? r[i] : NEG * r[i];

    *reinterpret_cast<float4*>(o)     = make_float4(r[0], r[1], r[2], r[3]);
    *reinterpret_cast<float4*>(o + 4) = make_float4(r[4], r[5], r[6], r[7]);
}

// ---------------------------------------------------------------------------
extern "C" void kernel_launch(void* const* d_in, const int* in_sizes, int n_in,
                              void* d_out, int out_size) {
    const float* x      = (const float*)d_in[0];
    const float* W      = (const float*)d_in[1];
    const float* a_src  = (const float*)d_in[2];
    const float* a_trg  = (const float*)d_in[3];
    const float* skip_w = (const float*)d_in[4];
    const float* bias   = (const float*)d_in[5];
    const int*   esrc   = (const int*)d_in[6];
    const int*   etrg   = (const int*)d_in[7];
    float*       out    = (float*)d_out;

    static cudaStream_t s_csr = nullptr;
    static cudaEvent_t  ev_fork = nullptr, ev_join = nullptr;
    static void* proj_ptr = nullptr;
    static void* deg_ptr  = nullptr;
    if (!s_csr) {
        cudaStreamCreateWithFlags(&s_csr, cudaStreamNonBlocking);
        cudaEventCreateWithFlags(&ev_fork, cudaEventDisableTiming);
        cudaEventCreateWithFlags(&ev_join, cudaEventDisableTiming);
        cudaGetSymbolAddress(&proj_ptr, g_proj);
        cudaGetSymbolAddress(&deg_ptr,  g_deg);
        cudaFuncSetAttribute(gemm_tf32_kernel,
                             cudaFuncAttributeMaxDynamicSharedMemorySize,
                             GEMM_SMEM);
    }

    // ---- fork: CSR build on side stream (hidden under the GEMM) ----
    cudaEventRecord(ev_fork, 0);
    cudaStreamWaitEvent(s_csr, ev_fork, 0);
    cudaMemsetAsync(deg_ptr, 0, N_NODES * sizeof(int), s_csr);
    count_kernel  <<<(N_EDGES + 255) / 256, 256, 0, s_csr>>>(etrg);
    scan_kernel   <<<1, SCAN_T, 0, s_csr>>>();
    scatter_kernel<<<(N_EDGES + 255) / 256, 256, 0, s_csr>>>(esrc, etrg);
    cudaEventRecord(ev_join, s_csr);

    // ---- main stream: B->tf32, fused GEMMs (+scores) ----
    bcvt_kernel<<<512, 256>>>(W, skip_w);
    dim3 ggrid((N_NODES + 127) / 128, 4);
    gemm_tf32_kernel<<<ggrid, 256, GEMM_SMEM>>>(x, (float*)proj_ptr, out,
                                                a_src, a_trg, N_NODES);

    // ---- join, then aggregate ----
    cudaStreamWaitEvent(0, ev_join, 0);
    agg_kernel<<<(N_NODES * 32 + 255) / 256, 256>>>(out, bias);
}